// round 2
// baseline (speedup 1.0000x reference)
#include <cuda_runtime.h>
#include <math.h>

// Problem shapes (fixed by setup_inputs)
#define BB 2
#define TT 512
#define MMs 512
#define DDim 512
#define HH 8
#define UU 64
#define OO 512
#define KVL 1024          // MMs + TT
#define NREL 1535         // KVL + TT - 1
#define LARGE_BIAS 10000.0f

// ---------------- scratch (static device globals; no allocation) ----------------
__device__ float g_S[NREL * DDim];                 // sinusoid table S[rel+511][d]   (3.1 MB)
__device__ float g_concat[BB * KVL * DDim];        // [state; inputs]                (4 MB)
__device__ float g_query[BB * TT * HH * UU];       // masked query (B,T,H,U)         (2 MB)
__device__ float g_key[BB * KVL * HH * UU];        // (B,KV,H,U)                     (4 MB)
__device__ float g_value[BB * KVL * HH * UU];      // (B,KV,H,U)                     (4 MB)
__device__ float g_relT[HH * UU * DDim];           // rel_W transposed to (h,u,d)    (1 MB)
__device__ float g_vrel[HH * DDim];                // v @ rel_W^T per head
__device__ float g_qv[BB * TT * HH * DDim];        // (B,T,H,D)                      (16 MB)
__device__ float g_ubias[BB * HH * KVL];           // key . u
__device__ float g_logits[BB * HH * TT * KVL];     // (B,H,T,KV) logits -> weights   (32 MB)
__device__ float g_att[BB * TT * HH * UU];         // attended (B,T,(H,U))           (2 MB)

// ---------------- table / prep kernels ----------------

// S[r][d] = sin((r-511)/wave_d + (pi/2)*(d&1)),  wave_d = 10000^(2d/512)
__global__ void k_tables() {
    int idx = blockIdx.x * blockDim.x + threadIdx.x;
    if (idx >= NREL * DDim) return;
    int r = idx / DDim;
    int d = idx - r * DDim;
    float rel = (float)(r - 511);
    float wave = powf(10000.0f, (2.0f * (float)d) / (float)DDim);
    float off  = (d & 1) ? 1.57079632679489662f : 0.0f;
    g_S[idx] = sinf(rel / wave + off);
}

__global__ void k_concat(const float* __restrict__ inputs, const float* __restrict__ state) {
    int idx = blockIdx.x * blockDim.x + threadIdx.x;
    if (idx >= BB * KVL * DDim) return;
    int d = idx & (DDim - 1);
    int j = (idx >> 9) & (KVL - 1);
    int b = idx >> 19;
    float v;
    if (j < MMs) v = state[((size_t)(b * MMs + j)) * DDim + d];
    else         v = inputs[((size_t)(b * TT + (j - MMs))) * DDim + d];
    g_concat[idx] = v;
}

// rel_W (d, h, u) -> g_relT (h, u, d)
__global__ void k_relT(const float* __restrict__ rW) {
    int idx = blockIdx.x * blockDim.x + threadIdx.x;
    if (idx >= DDim * HH * UU) return;
    int hu = idx & 511;
    int d  = idx >> 9;
    g_relT[(size_t)hu * DDim + d] = rW[idx];
}

// vrel[h][d] = sum_u v[h,u] * rel_W[d,h,u]
__global__ void k_vrel(const float* __restrict__ vv, const float* __restrict__ rW) {
    int idx = blockIdx.x * blockDim.x + threadIdx.x;
    if (idx >= HH * DDim) return;
    int h = idx >> 9;
    int d = idx & 511;
    const float* rp = rW + (size_t)d * (HH * UU) + h * UU;
    const float* vp = vv + h * UU;
    float s = 0.f;
#pragma unroll
    for (int u = 0; u < UU; u++) s = fmaf(rp[u], vp[u], s);
    g_vrel[idx] = s;
}

// ubias[(b,h,kv)] = sum_u key[b,kv,h,u] * u[h,u]
__global__ void k_ubias(const float* __restrict__ uW) {
    int idx = blockIdx.x * blockDim.x + threadIdx.x;
    if (idx >= BB * HH * KVL) return;
    int kv = idx & (KVL - 1);
    int h  = (idx >> 10) & (HH - 1);
    int b  = idx >> 13;
    const float* kp = g_key + ((size_t)(b * KVL + kv)) * (HH * UU) + h * UU;
    const float* up = uW + h * UU;
    float s = 0.f;
#pragma unroll
    for (int u = 0; u < UU; u++) s = fmaf(kp[u], up[u], s);
    g_ubias[idx] = s;
}

// ---------------- generic fp32 tiled GEMM: C = A @ B (+bias) (*rowmask) ----------------
// rowmask is int32 (bool inputs are materialized as int32 by the harness).
__global__ void __launch_bounds__(256) gemm64(
    const float* __restrict__ A, const float* __restrict__ Bm, float* __restrict__ C,
    int lda, int ldbk, int ldc, int Kdim,
    long a0, long b0, long c0,
    long az1, long az2, long bz1, long bz2, long cz1, long cz2,
    int Z2,
    const int* __restrict__ rowmask,
    const float* __restrict__ bias, long bias0, long biasz2)
{
    __shared__ float sA[16 * 64];
    __shared__ float sB[16 * 64];

    int z  = blockIdx.z;
    int z1 = z / Z2;
    int z2 = z - z1 * Z2;
    const float* Ap = A + a0 + (size_t)z1 * az1 + (size_t)z2 * az2;
    const float* Bp = Bm + b0 + (size_t)z1 * bz1 + (size_t)z2 * bz2;
    float*       Cp = C + c0 + (size_t)z1 * cz1 + (size_t)z2 * cz2;
    const float* biasp = bias ? (bias + bias0 + (size_t)z2 * biasz2) : (const float*)0;

    int m0 = blockIdx.y * 64;
    int n0 = blockIdx.x * 64;
    int tid = threadIdx.x;
    int tx = tid & 15, ty = tid >> 4;
    int am = tid >> 2, ak = (tid & 3) * 4;      // A loader: row am, k-group ak
    int bk = tid >> 4, bn = (tid & 15) * 4;     // B loader: k-row bk, n-group bn

    float acc[4][4];
#pragma unroll
    for (int i = 0; i < 4; i++)
#pragma unroll
        for (int j = 0; j < 4; j++) acc[i][j] = 0.f;

    for (int k0 = 0; k0 < Kdim; k0 += 16) {
        float4 av = *(const float4*)(Ap + (size_t)(m0 + am) * lda + (k0 + ak));
        float4 bv = *(const float4*)(Bp + (size_t)(k0 + bk) * ldbk + (n0 + bn));
        __syncthreads();
        sA[(ak + 0) * 64 + am] = av.x;
        sA[(ak + 1) * 64 + am] = av.y;
        sA[(ak + 2) * 64 + am] = av.z;
        sA[(ak + 3) * 64 + am] = av.w;
        *(float4*)&sB[bk * 64 + bn] = bv;
        __syncthreads();
#pragma unroll
        for (int kk = 0; kk < 16; kk++) {
            float4 a4 = *(const float4*)&sA[kk * 64 + ty * 4];
            float4 b4 = *(const float4*)&sB[kk * 64 + tx * 4];
            float a[4] = {a4.x, a4.y, a4.z, a4.w};
            float bb[4] = {b4.x, b4.y, b4.z, b4.w};
#pragma unroll
            for (int i = 0; i < 4; i++)
#pragma unroll
                for (int j = 0; j < 4; j++) acc[i][j] = fmaf(a[i], bb[j], acc[i][j]);
        }
    }

#pragma unroll
    for (int i = 0; i < 4; i++) {
        int mg = m0 + ty * 4 + i;
        float scale = 1.f;
        if (rowmask) scale = rowmask[mg] ? 1.f : 0.f;
        float4 o;
        float vals[4];
#pragma unroll
        for (int j = 0; j < 4; j++) {
            float v = acc[i][j];
            if (biasp) v += biasp[n0 + tx * 4 + j];
            vals[j] = v * scale;
        }
        o.x = vals[0]; o.y = vals[1]; o.z = vals[2]; o.w = vals[3];
        *(float4*)&Cp[(size_t)mg * ldc + n0 + tx * 4] = o;
    }
}

// ---------------- fused logits kernel ----------------
// logits[b,h,qt,kv] = ( Q.K^T + qv . S[qt-kv+512] + ubias[b,h,kv] ) / 8
//                     - causal LARGE - padding LARGE
__global__ void __launch_bounds__(256) k_logits(
    const int* __restrict__ qmask,
    const int* __restrict__ smask)
{
    __shared__ float sA[16 * 64];
    __shared__ float sB[2176];      // phase A: key tile (16x64); phase B: S band 127 rows x 17 (padded)

    int tid = threadIdx.x;
    int tx = tid & 15, ty = tid >> 4;
    int kv0 = blockIdx.x * 64;
    int qt0 = blockIdx.y * 64;
    int z = blockIdx.z;
    int b = z >> 3, h = z & 7;
    int am = tid >> 2, ak = (tid & 3) * 4;

    float acc[4][4];
#pragma unroll
    for (int i = 0; i < 4; i++)
#pragma unroll
        for (int j = 0; j < 4; j++) acc[i][j] = 0.f;

    // ---- phase A: content term, K = U = 64 ----
    const float* Qb = g_query + (size_t)(b * TT) * (HH * UU) + h * UU;
    const float* Kb = g_key   + (size_t)(b * KVL) * (HH * UU) + h * UU;
    for (int k0 = 0; k0 < UU; k0 += 16) {
        float4 qa = *(const float4*)(Qb + (size_t)(qt0 + am) * (HH * UU) + (k0 + ak));
        float4 ka = *(const float4*)(Kb + (size_t)(kv0 + am) * (HH * UU) + (k0 + ak));
        __syncthreads();
        sA[(ak + 0) * 64 + am] = qa.x;
        sA[(ak + 1) * 64 + am] = qa.y;
        sA[(ak + 2) * 64 + am] = qa.z;
        sA[(ak + 3) * 64 + am] = qa.w;
        sB[(ak + 0) * 64 + am] = ka.x;
        sB[(ak + 1) * 64 + am] = ka.y;
        sB[(ak + 2) * 64 + am] = ka.z;
        sB[(ak + 3) * 64 + am] = ka.w;
        __syncthreads();
#pragma unroll
        for (int kk = 0; kk < 16; kk++) {
            float4 a4 = *(const float4*)&sA[kk * 64 + ty * 4];
            float4 b4 = *(const float4*)&sB[kk * 64 + tx * 4];
            float a[4] = {a4.x, a4.y, a4.z, a4.w};
            float bb[4] = {b4.x, b4.y, b4.z, b4.w};
#pragma unroll
            for (int i = 0; i < 4; i++)
#pragma unroll
                for (int j = 0; j < 4; j++) acc[i][j] = fmaf(a[i], bb[j], acc[i][j]);
        }
    }

    // ---- phase B: banded position term, K = D = 512 ----
    // table row index = qt - kv + 1023 = rbase + relLocal; relLocal = 63 + (ty-tx)*4 + i - j
    const float* QVb = g_qv + (size_t)(b * TT) * (HH * DDim) + h * DDim;
    int rbase = qt0 - kv0 + 960;
    int rrow = (ty - tx) * 4 + 63;   // relLocal at i=j=0

    for (int k0 = 0; k0 < DDim; k0 += 16) {
        float4 qa = *(const float4*)(QVb + (size_t)(qt0 + am) * (HH * DDim) + (k0 + ak));
        // S band: 127 rows x 16 cols = 508 float4 groups; two rounds of 256 threads
        int r0 = tid >> 2, kq0 = (tid & 3) * 4;
        float4 s0 = *(const float4*)(g_S + (size_t)(rbase + r0) * DDim + k0 + kq0);
        int idx1 = tid + 256;
        int r1 = idx1 >> 2, kq1 = (idx1 & 3) * 4;
        float4 s1 = make_float4(0.f, 0.f, 0.f, 0.f);
        bool has1 = (idx1 < 508);
        if (has1) s1 = *(const float4*)(g_S + (size_t)(rbase + r1) * DDim + k0 + kq1);
        __syncthreads();
        sA[(ak + 0) * 64 + am] = qa.x;
        sA[(ak + 1) * 64 + am] = qa.y;
        sA[(ak + 2) * 64 + am] = qa.z;
        sA[(ak + 3) * 64 + am] = qa.w;
        sB[r0 * 17 + kq0 + 0] = s0.x;
        sB[r0 * 17 + kq0 + 1] = s0.y;
        sB[r0 * 17 + kq0 + 2] = s0.z;
        sB[r0 * 17 + kq0 + 3] = s0.w;
        if (has1) {
            sB[r1 * 17 + kq1 + 0] = s1.x;
            sB[r1 * 17 + kq1 + 1] = s1.y;
            sB[r1 * 17 + kq1 + 2] = s1.z;
            sB[r1 * 17 + kq1 + 3] = s1.w;
        }
        __syncthreads();
#pragma unroll
        for (int kk = 0; kk < 16; kk++) {
            float4 a4 = *(const float4*)&sA[kk * 64 + ty * 4];
            float a[4] = {a4.x, a4.y, a4.z, a4.w};
            float sv[7];
#pragma unroll
            for (int d = 0; d < 7; d++) sv[d] = sB[(rrow + d - 3) * 17 + kk];
#pragma unroll
            for (int i = 0; i < 4; i++)
#pragma unroll
                for (int j = 0; j < 4; j++) acc[i][j] = fmaf(a[i], sv[i - j + 3], acc[i][j]);
        }
    }

    // ---- epilogue: ubias, scale, masks ----
    float* Lb = g_logits + ((size_t)z * TT) * KVL;
#pragma unroll
    for (int i = 0; i < 4; i++) {
        int qt = qt0 + ty * 4 + i;
        float4 o;
        float vals[4];
#pragma unroll
        for (int j = 0; j < 4; j++) {
            int kv = kv0 + tx * 4 + j;
            float ub = g_ubias[(size_t)z * KVL + kv];
            float v = (acc[i][j] + ub) * 0.125f;
            if (kv - qt >= (KVL - TT + 1)) v -= LARGE_BIAS;   // causal triu, k = 513
            int cm = (kv < MMs) ? smask[b * MMs + kv]
                                : qmask[b * TT + (kv - MMs)];
            if (!cm) v -= LARGE_BIAS;                         // key padding
            vals[j] = v;
        }
        o.x = vals[0]; o.y = vals[1]; o.z = vals[2]; o.w = vals[3];
        *(float4*)&Lb[(size_t)qt * KVL + kv0 + tx * 4] = o;
    }
}

// ---------------- softmax over kv (in place on g_logits) ----------------
__global__ void __launch_bounds__(256) k_softmax() {
    float* row = g_logits + (size_t)blockIdx.x * KVL;
    int tid = threadIdx.x;
    int lane = tid & 31, wid = tid >> 5;
    __shared__ float red[8];
    __shared__ float bc;

    float v[4];
    float mx = -1e30f;
#pragma unroll
    for (int i = 0; i < 4; i++) {
        v[i] = row[tid + i * 256];
        mx = fmaxf(mx, v[i]);
    }
#pragma unroll
    for (int o = 16; o > 0; o >>= 1) mx = fmaxf(mx, __shfl_xor_sync(0xffffffff, mx, o));
    if (lane == 0) red[wid] = mx;
    __syncthreads();
    if (wid == 0) {
        float m2 = (lane < 8) ? red[lane] : -1e30f;
#pragma unroll
        for (int o = 16; o > 0; o >>= 1) m2 = fmaxf(m2, __shfl_xor_sync(0xffffffff, m2, o));
        if (lane == 0) bc = m2;
    }
    __syncthreads();
    mx = bc;

    float s = 0.f;
#pragma unroll
    for (int i = 0; i < 4; i++) {
        v[i] = expf(v[i] - mx);
        s += v[i];
    }
#pragma unroll
    for (int o = 16; o > 0; o >>= 1) s += __shfl_xor_sync(0xffffffff, s, o);
    __syncthreads();   // red[] reuse
    if (lane == 0) red[wid] = s;
    __syncthreads();
    if (wid == 0) {
        float s2 = (lane < 8) ? red[lane] : 0.f;
#pragma unroll
        for (int o = 16; o > 0; o >>= 1) s2 += __shfl_xor_sync(0xffffffff, s2, o);
        if (lane == 0) bc = s2;
    }
    __syncthreads();
    float inv = 1.f / bc;
#pragma unroll
    for (int i = 0; i < 4; i++) row[tid + i * 256] = v[i] * inv;
}

// ---------------- host launch ----------------
static float* symaddr(const void* sym) {
    void* p = 0;
    cudaGetSymbolAddress(&p, sym);
    return (float*)p;
}

extern "C" void kernel_launch(void* const* d_in, const int* in_sizes, int n_in,
                              void* d_out, int out_size) {
    (void)in_sizes; (void)n_in; (void)out_size;
    const float* inputs = (const float*)d_in[0];
    const float* state  = (const float*)d_in[1];
    const int* mask     = (const int*)d_in[2];    // bool inputs arrive as int32
    const int* smask    = (const int*)d_in[3];
    const float* qW     = (const float*)d_in[4];
    const float* kW     = (const float*)d_in[5];
    const float* rW     = (const float*)d_in[6];
    const float* vW     = (const float*)d_in[7];
    const float* uW     = (const float*)d_in[8];
    const float* vv     = (const float*)d_in[9];
    const float* oW     = (const float*)d_in[10];
    float* out = (float*)d_out;

    float* pConcat = symaddr(g_concat);
    float* pQuery  = symaddr(g_query);
    float* pKey    = symaddr(g_key);
    float* pValue  = symaddr(g_value);
    float* pRelT   = symaddr(g_relT);
    float* pVrel   = symaddr(g_vrel);
    float* pQv     = symaddr(g_qv);
    float* pLogits = symaddr(g_logits);
    float* pAtt    = symaddr(g_att);

    // prep
    k_tables<<<(NREL * DDim + 255) / 256, 256>>>();
    k_concat<<<(BB * KVL * DDim + 255) / 256, 256>>>(inputs, state);
    k_relT<<<(DDim * HH * UU + 255) / 256, 256>>>(rW);
    k_vrel<<<(HH * DDim + 255) / 256, 256>>>(vv, rW);

    // query = inputs @ qW, masked.  M=1024 N=512 K=512
    gemm64<<<dim3(8, 16, 1), 256>>>(inputs, qW, pQuery,
        512, 512, 512, 512,
        0, 0, 0,  0, 0, 0, 0, 0, 0,  1,
        mask, (const float*)0, 0, 0);

    // key / value = concat @ W.  M=2048 N=512 K=512
    gemm64<<<dim3(8, 32, 1), 256>>>(pConcat, kW, pKey,
        512, 512, 512, 512,
        0, 0, 0,  0, 0, 0, 0, 0, 0,  1,
        (const int*)0, (const float*)0, 0, 0);
    gemm64<<<dim3(8, 32, 1), 256>>>(pConcat, vW, pValue,
        512, 512, 512, 512,
        0, 0, 0,  0, 0, 0, 0, 0, 0,  1,
        (const int*)0, (const float*)0, 0, 0);

    // qv[b,t,h,:] = query_h @ relT_h + vrel_h.  per-h: M=1024 N=512 K=64
    gemm64<<<dim3(8, 16, HH), 256>>>(pQuery, pRelT, pQv,
        512, 512, 4096, 64,
        0, 0, 0,
        0, 64,               // A z2-stride: h*64
        0, (long)UU * DDim,  // B z2-stride: h*U*D
        0, 512,              // C z2-stride: h*512
        HH,
        (const int*)0, pVrel, 0, 512);

    k_ubias<<<(BB * HH * KVL + 255) / 256, 256>>>(uW);

    // fused logits (content + banded pos + bias + masks)
    k_logits<<<dim3(KVL / 64, TT / 64, BB * HH), 256>>>(mask, smask);

    // softmax over kv
    k_softmax<<<BB * HH * TT, 256>>>();

    // attended = weights @ value.  per-(b,h): M=512 N=64 K=1024
    gemm64<<<dim3(1, 8, BB * HH), 256>>>(pLogits, pValue, pAtt,
        KVL, 512, 512, KVL,
        0, 0, 0,
        (long)HH * TT * KVL, (long)TT * KVL,   // A: b, h strides
        (long)KVL * 512,     64,               // B (value): b, h strides
        (long)TT * 512,      64,               // C (att): b, h strides
        HH,
        (const int*)0, (const float*)0, 0, 0);

    // out = attended @ output_W.  M=1024 N=512 K=512
    gemm64<<<dim3(8, 16, 1), 256>>>(pAtt, oW, out,
        512, 512, 512, 512,
        0, 0, 0,  0, 0, 0, 0, 0, 0,  1,
        (const int*)0, (const float*)0, 0, 0);
}